// round 2
// baseline (speedup 1.0000x reference)
#include <cuda_runtime.h>
#include <math.h>

// Problem constants (fixed by the dataset)
#define NMAX 50000
#define EMAX 600000
#define FIN  64
#define HID  128

// ---------------------------------------------------------------------------
// Scratch (device globals; no allocation allowed in kernel_launch)
// ---------------------------------------------------------------------------
__device__ float g_dis[NMAX];            // deg, then d^{-1/2}
__device__ float g_w[EMAX];              // normalized edge weights
__device__ float g_T1[NMAX * FIN];
__device__ float g_T2[NMAX * FIN];
__device__ float g_T3[NMAX * FIN];
__device__ float g_Wcat[256 * 256];      // [k_in 0..255][col 0..255]; col<128 -> Z, else H
__device__ float g_bias[256];            // bxz+bhz | bxh+bhh

// ---------------------------------------------------------------------------
// Small utility kernels (reference device globals directly — kernel_launch
// contains nothing but kernel launches)
// ---------------------------------------------------------------------------
__global__ void k_zero_dis(int n) {
    int i = blockIdx.x * blockDim.x + threadIdx.x;
    if (i < n) g_dis[i] = 0.0f;
}

// which: 1 -> T1 = 0 ; 2 -> T2 = -x ; 3 -> T3 = -T1
__global__ void k_init(const float4* __restrict__ x, int which, int n4) {
    int i = blockIdx.x * blockDim.x + threadIdx.x;
    if (i >= n4) return;
    if (which == 1) {
        reinterpret_cast<float4*>(g_T1)[i] = make_float4(0.f, 0.f, 0.f, 0.f);
    } else if (which == 2) {
        float4 v = x[i];
        reinterpret_cast<float4*>(g_T2)[i] = make_float4(-v.x, -v.y, -v.z, -v.w);
    } else {
        float4 v = reinterpret_cast<const float4*>(g_T1)[i];
        reinterpret_cast<float4*>(g_T3)[i] = make_float4(-v.x, -v.y, -v.z, -v.w);
    }
}

// deg[src] += ew (self-loops removed)
__global__ void k_deg(const int* __restrict__ ei, const float* __restrict__ ew, int e) {
    int i = blockIdx.x * blockDim.x + threadIdx.x;
    if (i >= e) return;
    int s = ei[i], d = ei[e + i];
    if (s != d) atomicAdd(&g_dis[s], ew[i]);
}

__global__ void k_dis(int n) {
    int i = blockIdx.x * blockDim.x + threadIdx.x;
    if (i < n) {
        float dg = g_dis[i];
        g_dis[i] = (dg > 0.f) ? rsqrtf(dg) : 0.f;
    }
}

// w[e] = -dis[src]*ew*dis[dst], zero on self loops
__global__ void k_edgew(const int* __restrict__ ei, const float* __restrict__ ew, int e) {
    int i = blockIdx.x * blockDim.x + threadIdx.x;
    if (i >= e) return;
    int s = ei[i], d = ei[e + i];
    g_w[i] = (s == d) ? 0.f : -g_dis[s] * ew[i] * g_dis[d];
}

// ---------------------------------------------------------------------------
// SpMM propagation: out[dst] += (scale * w_e) * in[src], width 64.
// 16 threads per edge, one float4 each, vector reduction (sm_90+ red.v4.f32).
// which selects in/out from device globals: 1: x->T1, 2: T1->T2, 3: T2->T3.
// ---------------------------------------------------------------------------
__global__ __launch_bounds__(256) void k_prop(const float* __restrict__ x,
                                              const int* __restrict__ ei,
                                              int which, float scale, int e) {
    int t = blockIdx.x * blockDim.x + threadIdx.x;
    int edge = t >> 4;
    if (edge >= e) return;
    float wv = g_w[edge] * scale;
    if (wv == 0.f) return;
    int lane = t & 15;
    int s = ei[edge], d = ei[e + edge];
    const float* in = (which == 1) ? x : (which == 2) ? g_T1 : g_T2;
    float* out = (which == 1) ? g_T1 : (which == 2) ? g_T2 : g_T3;
    float4 v = __ldg(reinterpret_cast<const float4*>(in) + s * 16 + lane);
    float* op = out + d * 64 + lane * 4;
    asm volatile("red.global.add.v4.f32 [%0], {%1,%2,%3,%4};"
                 :: "l"(op), "f"(v.x * wv), "f"(v.y * wv), "f"(v.z * wv), "f"(v.w * wv)
                 : "memory");
}

// ---------------------------------------------------------------------------
// Build concatenated weight matrix [256 x 256] and bias vector.
// Wxz/Wxh are [K=4][64][128] row-major; k_in = kb*64 + f.
// ---------------------------------------------------------------------------
__global__ void k_wcat(const float* __restrict__ Wxz, const float* __restrict__ Wxh,
                       const float* __restrict__ bxz, const float* __restrict__ bhz,
                       const float* __restrict__ bxh, const float* __restrict__ bhh) {
    int idx = blockIdx.x * blockDim.x + threadIdx.x;
    if (idx < 256 * 256) {
        int kin = idx >> 8;
        int col = idx & 255;
        int kb = kin >> 6, f = kin & 63;
        float v;
        if (col < 128) v = Wxz[kb * 64 * 128 + f * 128 + col];
        else           v = Wxh[kb * 64 * 128 + f * 128 + (col - 128)];
        g_Wcat[kin * 256 + col] = v;
    }
    if (idx < 256) {
        g_bias[idx] = (idx < 128) ? (bxz[idx] + bhz[idx])
                                  : (bxh[idx - 128] + bhh[idx - 128]);
    }
}

// ---------------------------------------------------------------------------
// Fused GEMM + GRU epilogue + linear head.
//   pre[r, :] = sum_{kb} T_kb[r, :] @ Wcat[kb*64 : kb*64+64, :]
//   z = pre[:, :128] + bias_z ; ht = pre[:, 128:] + bias_h
//   out[r] = sum_j relu( sigmoid(-z_j) * tanh(ht_j) ) * linW[j] + linb
// Block tile: 64 rows x 256 cols, 256 threads, 8x8 per thread.
// Thread (warp w, lane c) owns rows w*8..w*8+7, cols {c*4..c*4+3, 128+c*4..+3}
// -> each thread holds the matched (z, h) pair; epilogue is warp-local.
// ---------------------------------------------------------------------------
__global__ __launch_bounds__(256) void k_gemm(const float* __restrict__ T0,
                                              const float* __restrict__ linW,
                                              const float* __restrict__ linb,
                                              float* __restrict__ out, int n) {
    __shared__ __align__(16) float As[32][68];   // [k][m], padded
    __shared__ __align__(16) float Bs[32 * 256]; // [k][col] flat

    int tid  = threadIdx.x;
    int warp = tid >> 5;
    int lane = tid & 31;
    int rbase = blockIdx.x * 64;

    float acc[8][8];
#pragma unroll
    for (int i = 0; i < 8; i++)
#pragma unroll
        for (int j = 0; j < 8; j++) acc[i][j] = 0.f;

    const float* srcs[4] = {T0, g_T1, g_T2, g_T3};
    int lm = tid >> 2;         // A-load row 0..63
    int lk = (tid & 3) * 8;    // A-load k offset {0,8,16,24}

    for (int kb = 0; kb < 4; kb++) {
        const float* A = srcs[kb];
        for (int kc = 0; kc < 64; kc += 32) {
            // stage A tile to registers
            float av[8];
            int grow = rbase + lm;
            if (grow < n) {
                float4 a0 = *reinterpret_cast<const float4*>(A + grow * 64 + kc + lk);
                float4 a1 = *reinterpret_cast<const float4*>(A + grow * 64 + kc + lk + 4);
                av[0] = a0.x; av[1] = a0.y; av[2] = a0.z; av[3] = a0.w;
                av[4] = a1.x; av[5] = a1.y; av[6] = a1.z; av[7] = a1.w;
            } else {
#pragma unroll
                for (int jj = 0; jj < 8; jj++) av[jj] = 0.f;
            }
            __syncthreads();  // previous tile fully consumed
#pragma unroll
            for (int jj = 0; jj < 8; jj++) As[lk + jj][lm] = av[jj];
            // stage B tile (flat contiguous copy of 32x256)
            const float4* Wsrc = reinterpret_cast<const float4*>(g_Wcat + (kb * 64 + kc) * 256);
            float4* Bd = reinterpret_cast<float4*>(Bs);
#pragma unroll
            for (int f = 0; f < 8; f++) Bd[tid + f * 256] = Wsrc[tid + f * 256];
            __syncthreads();

#pragma unroll 8
            for (int k = 0; k < 32; k++) {
                float4 a0 = *reinterpret_cast<const float4*>(&As[k][warp * 8]);
                float4 a1 = *reinterpret_cast<const float4*>(&As[k][warp * 8 + 4]);
                float4 b0 = *reinterpret_cast<const float4*>(&Bs[k * 256 + lane * 4]);
                float4 b1 = *reinterpret_cast<const float4*>(&Bs[k * 256 + 128 + lane * 4]);
                float a[8] = {a0.x, a0.y, a0.z, a0.w, a1.x, a1.y, a1.z, a1.w};
#pragma unroll
                for (int i = 0; i < 8; i++) {
                    acc[i][0] += a[i] * b0.x;
                    acc[i][1] += a[i] * b0.y;
                    acc[i][2] += a[i] * b0.z;
                    acc[i][3] += a[i] * b0.w;
                    acc[i][4] += a[i] * b1.x;
                    acc[i][5] += a[i] * b1.y;
                    acc[i][6] += a[i] * b1.z;
                    acc[i][7] += a[i] * b1.w;
                }
            }
        }
    }

    // epilogue: per-thread nonlinearity on matched (z,h), warp-reduce row dot
    float bz[4], bh[4], lw[4];
#pragma unroll
    for (int j = 0; j < 4; j++) {
        bz[j] = g_bias[lane * 4 + j];
        bh[j] = g_bias[128 + lane * 4 + j];
        lw[j] = __ldg(linW + lane * 4 + j);
    }
    float lb = __ldg(linb);

#pragma unroll
    for (int i = 0; i < 8; i++) {
        float partial = 0.f;
#pragma unroll
        for (int j = 0; j < 4; j++) {
            float z = acc[i][j]     + bz[j];
            float h = acc[i][4 + j] + bh[j];
            float th;
            asm("tanh.approx.f32 %0, %1;" : "=f"(th) : "f"(h));
            float s = 1.0f / (1.0f + __expf(z));   // == 1 - sigmoid(z)
            float val = fmaxf(s * th, 0.f);
            partial += val * lw[j];
        }
#pragma unroll
        for (int off = 16; off > 0; off >>= 1)
            partial += __shfl_xor_sync(0xffffffffu, partial, off);
        int row = rbase + warp * 8 + i;
        if (lane == 0 && row < n) out[row] = partial + lb;
    }
}

// ---------------------------------------------------------------------------
// kernel_launch — pure kernel launches, nothing else
// ---------------------------------------------------------------------------
extern "C" void kernel_launch(void* const* d_in, const int* in_sizes, int n_in,
                              void* d_out, int out_size) {
    (void)n_in; (void)out_size;
    const float* x    = (const float*)d_in[0];
    const int*   ei   = (const int*)d_in[1];
    const float* ew   = (const float*)d_in[2];
    const float* Wxz  = (const float*)d_in[3];
    const float* bxz  = (const float*)d_in[4];
    const float* bhz  = (const float*)d_in[6];
    const float* Wxh  = (const float*)d_in[11];
    const float* bxh  = (const float*)d_in[12];
    const float* bhh  = (const float*)d_in[14];
    const float* linW = (const float*)d_in[15];
    const float* linb = (const float*)d_in[16];
    float* out = (float*)d_out;

    int n = in_sizes[0] / FIN;   // 50000
    int e = in_sizes[2];         // 600000

    int n4 = n * (FIN / 4);      // float4 count of an N x 64 matrix
    int pgrid = (e * 16 + 255) / 256;

    // 1) normalization
    k_zero_dis<<<(n + 255) / 256, 256>>>(n);
    k_deg<<<(e + 255) / 256, 256>>>(ei, ew, e);
    k_dis<<<(n + 255) / 256, 256>>>(n);
    k_edgew<<<(e + 255) / 256, 256>>>(ei, ew, e);

    // 2) Chebyshev basis: T1 = P x ; T2 = 2 P T1 - x ; T3 = 2 P T2 - T1
    k_init<<<(n4 + 255) / 256, 256>>>((const float4*)x, 1, n4);
    k_prop<<<pgrid, 256>>>(x, ei, 1, 1.0f, e);
    k_init<<<(n4 + 255) / 256, 256>>>((const float4*)x, 2, n4);
    k_prop<<<pgrid, 256>>>(x, ei, 2, 2.0f, e);
    k_init<<<(n4 + 255) / 256, 256>>>((const float4*)x, 3, n4);
    k_prop<<<pgrid, 256>>>(x, ei, 3, 2.0f, e);

    // 3) weights concat (independent; any order)
    k_wcat<<<256, 256>>>(Wxz, Wxh, bxz, bhz, bxh, bhh);

    // 4) fused GEMM + GRU epilogue + linear head
    k_gemm<<<(n + 63) / 64, 256>>>(x, linW, linb, out, n);
}

// round 5
// speedup vs baseline: 1.3247x; 1.3247x over previous
#include <cuda_runtime.h>
#include <cstdint>
#include <math.h>

// Problem constants (fixed by the dataset)
#define NMAX 50000
#define EMAX 600000
#define FIN  64
#define HID  128

// ---------------------------------------------------------------------------
// Scratch (device globals; no allocation allowed in kernel_launch)
// ---------------------------------------------------------------------------
__device__ float g_dis[NMAX];              // deg, then d^{-1/2}
__device__ float g_w[EMAX];                // normalized edge weights
__device__ float g_T1[NMAX * FIN];
__device__ float g_T2[NMAX * FIN];
__device__ float g_T3[NMAX * FIN];
// B operand: [n' 0..255][k' 0..255], n' interleaved (even=z feat, odd=h feat),
// k' permuted within 8-groups so (k, k+4) are adjacent; values tf32-rounded.
__device__ float g_WcatT[256 * 256];
__device__ float g_bias[256];              // interleaved: [2j]=bz_j, [2j+1]=bh_j

// ---------------------------------------------------------------------------
// Small utility kernels
// ---------------------------------------------------------------------------
__global__ void k_zero_dis(int n) {
    int i = blockIdx.x * blockDim.x + threadIdx.x;
    if (i < n) g_dis[i] = 0.0f;
}

// which: 1 -> T1 = 0 ; 2 -> T2 = -x ; 3 -> T3 = -T1
__global__ void k_init(const float4* __restrict__ x, int which, int n4) {
    int i = blockIdx.x * blockDim.x + threadIdx.x;
    if (i >= n4) return;
    if (which == 1) {
        reinterpret_cast<float4*>(g_T1)[i] = make_float4(0.f, 0.f, 0.f, 0.f);
    } else if (which == 2) {
        float4 v = x[i];
        reinterpret_cast<float4*>(g_T2)[i] = make_float4(-v.x, -v.y, -v.z, -v.w);
    } else {
        float4 v = reinterpret_cast<const float4*>(g_T1)[i];
        reinterpret_cast<float4*>(g_T3)[i] = make_float4(-v.x, -v.y, -v.z, -v.w);
    }
}

__global__ void k_deg(const int* __restrict__ ei, const float* __restrict__ ew, int e) {
    int i = blockIdx.x * blockDim.x + threadIdx.x;
    if (i >= e) return;
    int s = ei[i], d = ei[e + i];
    if (s != d) atomicAdd(&g_dis[s], ew[i]);
}

__global__ void k_dis(int n) {
    int i = blockIdx.x * blockDim.x + threadIdx.x;
    if (i < n) {
        float dg = g_dis[i];
        g_dis[i] = (dg > 0.f) ? rsqrtf(dg) : 0.f;
    }
}

__global__ void k_edgew(const int* __restrict__ ei, const float* __restrict__ ew, int e) {
    int i = blockIdx.x * blockDim.x + threadIdx.x;
    if (i >= e) return;
    int s = ei[i], d = ei[e + i];
    g_w[i] = (s == d) ? 0.f : -g_dis[s] * ew[i] * g_dis[d];
}

// ---------------------------------------------------------------------------
// SpMM propagation: out[dst] += (scale * w_e) * in[src], width 64.
// ---------------------------------------------------------------------------
__global__ __launch_bounds__(256) void k_prop(const float* __restrict__ x,
                                              const int* __restrict__ ei,
                                              int which, float scale, int e) {
    int t = blockIdx.x * blockDim.x + threadIdx.x;
    int edge = t >> 4;
    if (edge >= e) return;
    float wv = g_w[edge] * scale;
    if (wv == 0.f) return;
    int lane = t & 15;
    int s = ei[edge], d = ei[e + edge];
    const float* in = (which == 1) ? x : (which == 2) ? g_T1 : g_T2;
    float* out = (which == 1) ? g_T1 : (which == 2) ? g_T2 : g_T3;
    float4 v = __ldg(reinterpret_cast<const float4*>(in) + s * 16 + lane);
    float* op = out + d * 64 + lane * 4;
    asm volatile("red.global.add.v4.f32 [%0], {%1,%2,%3,%4};"
                 :: "l"(op), "f"(v.x * wv), "f"(v.y * wv), "f"(v.z * wv), "f"(v.w * wv)
                 : "memory");
}

// ---------------------------------------------------------------------------
// tf32 round helper — destination of cvt.*.tf32 must be a b32 register.
// The resulting bit pattern is a valid f32; reinterpret to carry in float mem.
// ---------------------------------------------------------------------------
__device__ __forceinline__ float tf32_rna(float v) {
    uint32_t r;
    asm("cvt.rna.tf32.f32 %0, %1;" : "=r"(r) : "f"(v));
    return __uint_as_float(r);
}

// ---------------------------------------------------------------------------
// Build W^T [n'][k'] with column interleave + k permutation + tf32 rounding.
//   n': even -> z feature n'/2 (from Wxz), odd -> h feature n'/2 (from Wxh)
//   k': group g = k'>>3, pos p = k'&7, original kk = (p>>1) + (p&1)*4,
//       k = g*8 + kk, kb = k>>6, f = k&63
// ---------------------------------------------------------------------------
__global__ void k_wcat(const float* __restrict__ Wxz, const float* __restrict__ Wxh,
                       const float* __restrict__ bxz, const float* __restrict__ bhz,
                       const float* __restrict__ bxh, const float* __restrict__ bhh) {
    int idx = blockIdx.x * blockDim.x + threadIdx.x;
    if (idx < 256 * 256) {
        int np = idx >> 8;
        int kp = idx & 255;
        int j = np >> 1;
        int g = kp >> 3, p = kp & 7;
        int kk = (p >> 1) + (p & 1) * 4;
        int k = g * 8 + kk;
        int kb = k >> 6, f = k & 63;
        float v = (np & 1) ? Wxh[kb * 64 * 128 + f * 128 + j]
                           : Wxz[kb * 64 * 128 + f * 128 + j];
        g_WcatT[np * 256 + kp] = tf32_rna(v);
    }
    if (idx < 256) {
        int j = idx >> 1;
        g_bias[idx] = (idx & 1) ? (bxh[j] + bhh[j]) : (bxz[j] + bhz[j]);
    }
}

// ---------------------------------------------------------------------------
// Legacy-mma tf32 GEMM + fused GRU epilogue + linear head.
//   CTA tile: 128(M) x 256(N), K=256 in 8 chunks of 32.
//   512 threads = 16 warps: wm = warp&3 (M), wn = warp>>2 (N).
//   Warp tile 32x64: mt 0..1 (m16), nt 0..7 (n8). mma.m16n8k8 tf32.
//   Columns interleaved: thread's (c0,c1)/(c2,c3) = matched (z_j, h_j).
// ---------------------------------------------------------------------------
#define A_STRIDE 40
#define B_STRIDE 40
#define SM_A_FLOATS (128 * A_STRIDE)
#define SM_B_FLOATS (256 * B_STRIDE)
#define SM_RED_FLOATS (128 * 4)
#define GEMM_SMEM ((SM_A_FLOATS + SM_B_FLOATS + SM_RED_FLOATS) * 4)

__device__ __forceinline__ void mma_tf32(float* d, uint32_t a0, uint32_t a1,
                                         uint32_t a2, uint32_t a3,
                                         uint32_t b0, uint32_t b1) {
    asm volatile(
        "mma.sync.aligned.m16n8k8.row.col.f32.tf32.tf32.f32 "
        "{%0,%1,%2,%3}, {%4,%5,%6,%7}, {%8,%9}, {%0,%1,%2,%3};"
        : "+f"(d[0]), "+f"(d[1]), "+f"(d[2]), "+f"(d[3])
        : "r"(a0), "r"(a1), "r"(a2), "r"(a3), "r"(b0), "r"(b1));
}

__global__ __launch_bounds__(512, 1) void k_gemm_mma(const float* __restrict__ x,
                                                     const float* __restrict__ linW,
                                                     const float* __restrict__ linb,
                                                     float* __restrict__ out, int n) {
    extern __shared__ __align__(16) float smem[];
    float* As  = smem;                       // [128][A_STRIDE], k' within chunk
    float* Bs  = As + SM_A_FLOATS;           // [256][B_STRIDE]
    float* red = Bs + SM_B_FLOATS;           // [128][4]

    int tid  = threadIdx.x;
    int warp = tid >> 5;
    int lane = tid & 31;
    int wm = warp & 3;       // m quadrant (32 rows)
    int wn = warp >> 2;      // n quadrant (64 interleaved cols = 32 features)
    int gid = lane >> 2;     // fragment row/col group 0..7
    int q   = lane & 3;      // fragment k / col-pair index
    int rbase = blockIdx.x * 128;

    float acc[2][8][4];
#pragma unroll
    for (int mt = 0; mt < 2; mt++)
#pragma unroll
        for (int nt = 0; nt < 8; nt++)
#pragma unroll
            for (int c = 0; c < 4; c++) acc[mt][nt][c] = 0.f;

    const float* srcs[4] = {x, g_T1, g_T2, g_T3};

    // staging assignments
    int a_row  = tid >> 2;          // 0..127
    int a_quad = tid & 3;           // k-group within chunk (8 k each)
    int b_row  = tid >> 1;          // 0..255
    int b_half = tid & 1;           // 16 k' each

    for (int c = 0; c < 8; c++) {
        __syncthreads();  // previous chunk fully consumed
        // ---- stage A chunk: rows 0..127, k = c*32 .. +32, permuted + tf32 ----
        {
            const float* src = srcs[c >> 1];
            int f0 = (c & 1) * 32 + a_quad * 8;
            float* dst = As + a_row * A_STRIDE + a_quad * 8;
            int grow = rbase + a_row;
            if (grow < n) {
                float4 v1 = __ldg(reinterpret_cast<const float4*>(src + grow * 64 + f0));
                float4 v2 = __ldg(reinterpret_cast<const float4*>(src + grow * 64 + f0 + 4));
                dst[0] = tf32_rna(v1.x); dst[2] = tf32_rna(v1.y);
                dst[4] = tf32_rna(v1.z); dst[6] = tf32_rna(v1.w);
                dst[1] = tf32_rna(v2.x); dst[3] = tf32_rna(v2.y);
                dst[5] = tf32_rna(v2.z); dst[7] = tf32_rna(v2.w);
            } else {
#pragma unroll
                for (int i = 0; i < 8; i++) dst[i] = 0.f;
            }
        }
        // ---- stage B chunk: n' 0..255, k' = c*32 .. +32 (already permuted) ----
        {
            const float4* src = reinterpret_cast<const float4*>(
                g_WcatT + b_row * 256 + c * 32 + b_half * 16);
            float* dst = Bs + b_row * B_STRIDE + b_half * 16;
#pragma unroll
            for (int j = 0; j < 4; j++) {
                float4 v = __ldg(src + j);
                *reinterpret_cast<float4*>(dst + j * 4) = v;
            }
        }
        __syncthreads();

        // ---- mma over 4 k-groups of 8 ----
#pragma unroll
        for (int g = 0; g < 4; g++) {
            uint32_t af[2][4];
#pragma unroll
            for (int mt = 0; mt < 2; mt++) {
                int r0 = wm * 32 + mt * 16 + gid;
                float2 lo = *reinterpret_cast<const float2*>(As + r0 * A_STRIDE + g * 8 + q * 2);
                float2 hi = *reinterpret_cast<const float2*>(As + (r0 + 8) * A_STRIDE + g * 8 + q * 2);
                af[mt][0] = __float_as_uint(lo.x);  // a0 = A[r][k=q]
                af[mt][2] = __float_as_uint(lo.y);  // a2 = A[r][k=q+4]
                af[mt][1] = __float_as_uint(hi.x);  // a1 = A[r+8][k=q]
                af[mt][3] = __float_as_uint(hi.y);  // a3 = A[r+8][k=q+4]
            }
#pragma unroll
            for (int nt = 0; nt < 8; nt++) {
                int nn = wn * 64 + nt * 8 + gid;
                float2 b = *reinterpret_cast<const float2*>(Bs + nn * B_STRIDE + g * 8 + q * 2);
                uint32_t b0 = __float_as_uint(b.x);  // B[k=q][n]
                uint32_t b1 = __float_as_uint(b.y);  // B[k=q+4][n]
#pragma unroll
                for (int mt = 0; mt < 2; mt++)
                    mma_tf32(acc[mt][nt], af[mt][0], af[mt][1], af[mt][2], af[mt][3], b0, b1);
            }
        }
    }

    // ---- fused epilogue ----
    // thread's features: j = wn*32 + nt*4 + q  (8 of them)
    float bz[8], bh[8], lw[8];
#pragma unroll
    for (int nt = 0; nt < 8; nt++) {
        int j = wn * 32 + nt * 4 + q;
        bz[nt] = __ldg(g_bias + 2 * j);
        bh[nt] = __ldg(g_bias + 2 * j + 1);
        lw[nt] = __ldg(linW + j);
    }
#pragma unroll
    for (int mt = 0; mt < 2; mt++) {
#pragma unroll
        for (int half = 0; half < 2; half++) {
            float p = 0.f;
#pragma unroll
            for (int nt = 0; nt < 8; nt++) {
                float z = acc[mt][nt][half * 2 + 0] + bz[nt];
                float h = acc[mt][nt][half * 2 + 1] + bh[nt];
                float th;
                asm("tanh.approx.f32 %0, %1;" : "=f"(th) : "f"(h));
                float sg = 1.0f / (1.0f + __expf(z));  // sigmoid(-z)
                p += fmaxf(sg * th, 0.f) * lw[nt];
            }
            p += __shfl_xor_sync(0xffffffffu, p, 1);
            p += __shfl_xor_sync(0xffffffffu, p, 2);
            if (q == 0) {
                int row = wm * 32 + mt * 16 + half * 8 + gid;  // 0..127
                red[row * 4 + wn] = p;
            }
        }
    }
    __syncthreads();
    if (tid < 128) {
        int row = rbase + tid;
        if (row < n) {
            float s = red[tid * 4] + red[tid * 4 + 1] + red[tid * 4 + 2] + red[tid * 4 + 3];
            out[row] = s + __ldg(linb);
        }
    }
}

// ---------------------------------------------------------------------------
// kernel_launch
// ---------------------------------------------------------------------------
extern "C" void kernel_launch(void* const* d_in, const int* in_sizes, int n_in,
                              void* d_out, int out_size) {
    (void)n_in; (void)out_size;
    const float* x    = (const float*)d_in[0];
    const int*   ei   = (const int*)d_in[1];
    const float* ew   = (const float*)d_in[2];
    const float* Wxz  = (const float*)d_in[3];
    const float* bxz  = (const float*)d_in[4];
    const float* bhz  = (const float*)d_in[6];
    const float* Wxh  = (const float*)d_in[11];
    const float* bxh  = (const float*)d_in[12];
    const float* bhh  = (const float*)d_in[14];
    const float* linW = (const float*)d_in[15];
    const float* linb = (const float*)d_in[16];
    float* out = (float*)d_out;

    int n = in_sizes[0] / FIN;   // 50000
    int e = in_sizes[2];         // 600000

    int n4 = n * (FIN / 4);
    int pgrid = (e * 16 + 255) / 256;

    // 1) normalization
    k_zero_dis<<<(n + 255) / 256, 256>>>(n);
    k_deg<<<(e + 255) / 256, 256>>>(ei, ew, e);
    k_dis<<<(n + 255) / 256, 256>>>(n);
    k_edgew<<<(e + 255) / 256, 256>>>(ei, ew, e);

    // 2) Chebyshev basis: T1 = P x ; T2 = 2 P T1 - x ; T3 = 2 P T2 - T1
    k_init<<<(n4 + 255) / 256, 256>>>((const float4*)x, 1, n4);
    k_prop<<<pgrid, 256>>>(x, ei, 1, 1.0f, e);
    k_init<<<(n4 + 255) / 256, 256>>>((const float4*)x, 2, n4);
    k_prop<<<pgrid, 256>>>(x, ei, 2, 2.0f, e);
    k_init<<<(n4 + 255) / 256, 256>>>((const float4*)x, 3, n4);
    k_prop<<<pgrid, 256>>>(x, ei, 3, 2.0f, e);

    // 3) weight concat (independent; any order)
    k_wcat<<<256, 256>>>(Wxz, Wxh, bxz, bhz, bxh, bhh);

    // 4) tf32 mma GEMM + GRU epilogue + linear head
    cudaFuncSetAttribute(k_gemm_mma, cudaFuncAttributeMaxDynamicSharedMemorySize,
                         GEMM_SMEM);
    k_gemm_mma<<<(n + 127) / 128, 512, GEMM_SMEM>>>(x, linW, linb, out, n);
}

// round 6
// speedup vs baseline: 1.4004x; 1.0571x over previous
#include <cuda_runtime.h>
#include <cstdint>
#include <math.h>

// Problem constants (fixed by the dataset)
#define NMAX 50000
#define EMAX 600000
#define FIN  64
#define HID  128

// ---------------------------------------------------------------------------
// Scratch (device globals; no allocation allowed in kernel_launch)
// ---------------------------------------------------------------------------
__device__ float g_dis[NMAX];              // deg, then d^{-1/2}
__device__ int   g_cnt[NMAX];              // in-degree histogram (by dst)
__device__ int   g_cur[NMAX];              // scatter cursors
__device__ int   g_row[NMAX + 1];          // CSR row offsets (by dst)
__device__ int   g_src2[EMAX];             // permuted src ids
__device__ float g_w2[EMAX];               // permuted normalized weights
__device__ float g_S1[NMAX * FIN];         // P x
__device__ float g_S2[NMAX * FIN];         // P^2 x
__device__ float g_S3[NMAX * FIN];         // P^3 x
// B operand: [n' 0..255][k' 0..255], n' interleaved (even=z feat, odd=h feat),
// k' permuted within 8-groups so (k, k+4) are adjacent; values tf32-rounded.
__device__ float g_WcatT[256 * 256];
__device__ float g_bias[256];              // interleaved: [2j]=bz_j, [2j+1]=bh_j

// ---------------------------------------------------------------------------
// Setup kernels
// ---------------------------------------------------------------------------
__global__ void k_zero_small(int n) {      // dis + cnt + cur
    int i = blockIdx.x * blockDim.x + threadIdx.x;
    if (i < n) { g_dis[i] = 0.0f; g_cnt[i] = 0; g_cur[i] = 0; }
}

// deg[src] += ew (self-loops removed) ; cnt[dst] += 1
__global__ void k_deg_hist(const int* __restrict__ ei, const float* __restrict__ ew, int e) {
    int i = blockIdx.x * blockDim.x + threadIdx.x;
    if (i >= e) return;
    int s = ei[i], d = ei[e + i];
    if (s != d) atomicAdd(&g_dis[s], ew[i]);
    atomicAdd(&g_cnt[d], 1);
}

__global__ void k_dis(int n) {
    int i = blockIdx.x * blockDim.x + threadIdx.x;
    if (i < n) {
        float dg = g_dis[i];
        g_dis[i] = (dg > 0.f) ? rsqrtf(dg) : 0.f;
    }
}

// Single-block exclusive scan of g_cnt[0..n) -> g_row[0..n]
#define SCAN_T 1024
__global__ __launch_bounds__(SCAN_T) void k_scan(int n) {
    __shared__ int warpsum[32];
    int tid = threadIdx.x;
    int lane = tid & 31, wid = tid >> 5;
    int chunk = (n + SCAN_T - 1) / SCAN_T;
    int beg = tid * chunk;
    int end = min(beg + chunk, n);
    int s = 0;
    for (int i = beg; i < end; i++) s += g_cnt[i];
    // block-wide exclusive scan of per-thread sums
    int v = s;
#pragma unroll
    for (int o = 1; o < 32; o <<= 1) {
        int t = __shfl_up_sync(0xffffffffu, v, o);
        if (lane >= o) v += t;
    }
    if (lane == 31) warpsum[wid] = v;
    __syncthreads();
    if (wid == 0) {
        int w = warpsum[lane];
#pragma unroll
        for (int o = 1; o < 32; o <<= 1) {
            int t = __shfl_up_sync(0xffffffffu, w, o);
            if (lane >= o) w += t;
        }
        warpsum[lane] = w;
    }
    __syncthreads();
    int excl = (v - s) + (wid ? warpsum[wid - 1] : 0);
    int run = excl;
    for (int i = beg; i < end; i++) { g_row[i] = run; run += g_cnt[i]; }
    if (beg < n && end == n) g_row[n] = run;
}

// w = -dis[src]*ew*dis[dst] (0 on self loops); scatter into CSR slots
__global__ void k_edgew_scatter(const int* __restrict__ ei, const float* __restrict__ ew, int e) {
    int i = blockIdx.x * blockDim.x + threadIdx.x;
    if (i >= e) return;
    int s = ei[i], d = ei[e + i];
    float w = (s == d) ? 0.f : -g_dis[s] * ew[i] * g_dis[d];
    int pos = g_row[d] + atomicAdd(&g_cur[d], 1);
    g_src2[pos] = s;
    g_w2[pos] = w;
}

// ---------------------------------------------------------------------------
// Gather SpMM: out[node] = sum_e w_e * in[src_e]  (one warp per node; no atomics)
// which: 1 -> x->S1 ; 2 -> S1->S2 ; 3 -> S2->S3
// ---------------------------------------------------------------------------
__global__ __launch_bounds__(256) void k_prop_csr(const float* __restrict__ x,
                                                  int which, int n) {
    int node = (blockIdx.x * blockDim.x + threadIdx.x) >> 5;
    if (node >= n) return;
    int lane = threadIdx.x & 31;
    const float* in = (which == 1) ? x : (which == 2) ? g_S1 : g_S2;
    float* out = (which == 1) ? g_S1 : (which == 2) ? g_S2 : g_S3;
    int beg = g_row[node], end = g_row[node + 1];
    float ax = 0.f, ay = 0.f;
    for (int e = beg; e < end; e++) {
        int s = __ldg(g_src2 + e);
        float wv = __ldg(g_w2 + e);
        float2 v = __ldg(reinterpret_cast<const float2*>(in + s * 64) + lane);
        ax += wv * v.x;
        ay += wv * v.y;
    }
    reinterpret_cast<float2*>(out + node * 64)[lane] = make_float2(ax, ay);
}

// ---------------------------------------------------------------------------
// tf32 round helper — destination of cvt.*.tf32 must be a b32 register.
// ---------------------------------------------------------------------------
__device__ __forceinline__ float tf32_rna(float v) {
    uint32_t r;
    asm("cvt.rna.tf32.f32 %0, %1;" : "=r"(r) : "f"(v));
    return __uint_as_float(r);
}

// ---------------------------------------------------------------------------
// Build W^T [n'][k'] with column interleave + k permutation + tf32 rounding.
// ---------------------------------------------------------------------------
__global__ void k_wcat(const float* __restrict__ Wxz, const float* __restrict__ Wxh,
                       const float* __restrict__ bxz, const float* __restrict__ bhz,
                       const float* __restrict__ bxh, const float* __restrict__ bhh) {
    int idx = blockIdx.x * blockDim.x + threadIdx.x;
    if (idx < 256 * 256) {
        int np = idx >> 8;
        int kp = idx & 255;
        int j = np >> 1;
        int g = kp >> 3, p = kp & 7;
        int kk = (p >> 1) + (p & 1) * 4;
        int k = g * 8 + kk;
        int kb = k >> 6, f = k & 63;
        float v = (np & 1) ? Wxh[kb * 64 * 128 + f * 128 + j]
                           : Wxz[kb * 64 * 128 + f * 128 + j];
        g_WcatT[np * 256 + kp] = tf32_rna(v);
    }
    if (idx < 256) {
        int j = idx >> 1;
        g_bias[idx] = (idx & 1) ? (bxh[j] + bhh[j]) : (bxz[j] + bhz[j]);
    }
}

// ---------------------------------------------------------------------------
// Legacy-mma tf32 GEMM + fused GRU epilogue + linear head.
// A columns built on the fly from power series:
//   kb0: x ; kb1: S1 ; kb2: 2*S2 - x ; kb3: 4*S3 - 3*S1
// ---------------------------------------------------------------------------
#define A_STRIDE 40
#define B_STRIDE 40
#define SM_A_FLOATS (128 * A_STRIDE)
#define SM_B_FLOATS (256 * B_STRIDE)
#define SM_RED_FLOATS (128 * 4)
#define GEMM_SMEM ((SM_A_FLOATS + SM_B_FLOATS + SM_RED_FLOATS) * 4)

__device__ __forceinline__ void mma_tf32(float* d, uint32_t a0, uint32_t a1,
                                         uint32_t a2, uint32_t a3,
                                         uint32_t b0, uint32_t b1) {
    asm volatile(
        "mma.sync.aligned.m16n8k8.row.col.f32.tf32.tf32.f32 "
        "{%0,%1,%2,%3}, {%4,%5,%6,%7}, {%8,%9}, {%0,%1,%2,%3};"
        : "+f"(d[0]), "+f"(d[1]), "+f"(d[2]), "+f"(d[3])
        : "r"(a0), "r"(a1), "r"(a2), "r"(a3), "r"(b0), "r"(b1));
}

__global__ __launch_bounds__(512, 1) void k_gemm_mma(const float* __restrict__ x,
                                                     const float* __restrict__ linW,
                                                     const float* __restrict__ linb,
                                                     float* __restrict__ out, int n) {
    extern __shared__ __align__(16) float smem[];
    float* As  = smem;                       // [128][A_STRIDE]
    float* Bs  = As + SM_A_FLOATS;           // [256][B_STRIDE]
    float* red = Bs + SM_B_FLOATS;           // [128][4]

    int tid  = threadIdx.x;
    int warp = tid >> 5;
    int lane = tid & 31;
    int wm = warp & 3;
    int wn = warp >> 2;
    int gid = lane >> 2;
    int q   = lane & 3;
    int rbase = blockIdx.x * 128;

    float acc[2][8][4];
#pragma unroll
    for (int mt = 0; mt < 2; mt++)
#pragma unroll
        for (int nt = 0; nt < 8; nt++)
#pragma unroll
            for (int c = 0; c < 4; c++) acc[mt][nt][c] = 0.f;

    int a_row  = tid >> 2;          // 0..127
    int a_quad = tid & 3;           // k-group within chunk (8 k each)
    int b_row  = tid >> 1;          // 0..255
    int b_half = tid & 1;           // 16 k' each

    for (int c = 0; c < 8; c++) {
        __syncthreads();  // previous chunk fully consumed
        // ---- stage A chunk: rows 0..127, k = c*32 .. +32, permuted + tf32 ----
        {
            int kb = c >> 1;
            int f0 = (c & 1) * 32 + a_quad * 8;
            float* dst = As + a_row * A_STRIDE + a_quad * 8;
            int grow = rbase + a_row;
            if (grow < n) {
                long off = (long)grow * 64 + f0;
                float4 v1, v2;
                if (kb == 0) {
                    v1 = __ldg(reinterpret_cast<const float4*>(x + off));
                    v2 = __ldg(reinterpret_cast<const float4*>(x + off + 4));
                } else if (kb == 1) {
                    v1 = __ldg(reinterpret_cast<const float4*>(g_S1 + off));
                    v2 = __ldg(reinterpret_cast<const float4*>(g_S1 + off + 4));
                } else if (kb == 2) {
                    float4 a1 = __ldg(reinterpret_cast<const float4*>(g_S2 + off));
                    float4 a2 = __ldg(reinterpret_cast<const float4*>(g_S2 + off + 4));
                    float4 b1 = __ldg(reinterpret_cast<const float4*>(x + off));
                    float4 b2 = __ldg(reinterpret_cast<const float4*>(x + off + 4));
                    v1 = make_float4(2.f * a1.x - b1.x, 2.f * a1.y - b1.y,
                                     2.f * a1.z - b1.z, 2.f * a1.w - b1.w);
                    v2 = make_float4(2.f * a2.x - b2.x, 2.f * a2.y - b2.y,
                                     2.f * a2.z - b2.z, 2.f * a2.w - b2.w);
                } else {
                    float4 a1 = __ldg(reinterpret_cast<const float4*>(g_S3 + off));
                    float4 a2 = __ldg(reinterpret_cast<const float4*>(g_S3 + off + 4));
                    float4 b1 = __ldg(reinterpret_cast<const float4*>(g_S1 + off));
                    float4 b2 = __ldg(reinterpret_cast<const float4*>(g_S1 + off + 4));
                    v1 = make_float4(4.f * a1.x - 3.f * b1.x, 4.f * a1.y - 3.f * b1.y,
                                     4.f * a1.z - 3.f * b1.z, 4.f * a1.w - 3.f * b1.w);
                    v2 = make_float4(4.f * a2.x - 3.f * b2.x, 4.f * a2.y - 3.f * b2.y,
                                     4.f * a2.z - 3.f * b2.z, 4.f * a2.w - 3.f * b2.w);
                }
                dst[0] = tf32_rna(v1.x); dst[2] = tf32_rna(v1.y);
                dst[4] = tf32_rna(v1.z); dst[6] = tf32_rna(v1.w);
                dst[1] = tf32_rna(v2.x); dst[3] = tf32_rna(v2.y);
                dst[5] = tf32_rna(v2.z); dst[7] = tf32_rna(v2.w);
            } else {
#pragma unroll
                for (int i = 0; i < 8; i++) dst[i] = 0.f;
            }
        }
        // ---- stage B chunk ----
        {
            const float4* src = reinterpret_cast<const float4*>(
                g_WcatT + b_row * 256 + c * 32 + b_half * 16);
            float* dst = Bs + b_row * B_STRIDE + b_half * 16;
#pragma unroll
            for (int j = 0; j < 4; j++) {
                float4 v = __ldg(src + j);
                *reinterpret_cast<float4*>(dst + j * 4) = v;
            }
        }
        __syncthreads();

        // ---- mma over 4 k-groups of 8 ----
#pragma unroll
        for (int g = 0; g < 4; g++) {
            uint32_t af[2][4];
#pragma unroll
            for (int mt = 0; mt < 2; mt++) {
                int r0 = wm * 32 + mt * 16 + gid;
                float2 lo = *reinterpret_cast<const float2*>(As + r0 * A_STRIDE + g * 8 + q * 2);
                float2 hi = *reinterpret_cast<const float2*>(As + (r0 + 8) * A_STRIDE + g * 8 + q * 2);
                af[mt][0] = __float_as_uint(lo.x);
                af[mt][2] = __float_as_uint(lo.y);
                af[mt][1] = __float_as_uint(hi.x);
                af[mt][3] = __float_as_uint(hi.y);
            }
#pragma unroll
            for (int nt = 0; nt < 8; nt++) {
                int nn = wn * 64 + nt * 8 + gid;
                float2 b = *reinterpret_cast<const float2*>(Bs + nn * B_STRIDE + g * 8 + q * 2);
                uint32_t b0 = __float_as_uint(b.x);
                uint32_t b1 = __float_as_uint(b.y);
#pragma unroll
                for (int mt = 0; mt < 2; mt++)
                    mma_tf32(acc[mt][nt], af[mt][0], af[mt][1], af[mt][2], af[mt][3], b0, b1);
            }
        }
    }

    // ---- fused epilogue ----
    float bz[8], bh[8], lw[8];
#pragma unroll
    for (int nt = 0; nt < 8; nt++) {
        int j = wn * 32 + nt * 4 + q;
        bz[nt] = __ldg(g_bias + 2 * j);
        bh[nt] = __ldg(g_bias + 2 * j + 1);
        lw[nt] = __ldg(linW + j);
    }
#pragma unroll
    for (int mt = 0; mt < 2; mt++) {
#pragma unroll
        for (int half = 0; half < 2; half++) {
            float p = 0.f;
#pragma unroll
            for (int nt = 0; nt < 8; nt++) {
                float z = acc[mt][nt][half * 2 + 0] + bz[nt];
                float h = acc[mt][nt][half * 2 + 1] + bh[nt];
                float th;
                asm("tanh.approx.f32 %0, %1;" : "=f"(th) : "f"(h));
                float sg = 1.0f / (1.0f + __expf(z));  // sigmoid(-z)
                p += fmaxf(sg * th, 0.f) * lw[nt];
            }
            p += __shfl_xor_sync(0xffffffffu, p, 1);
            p += __shfl_xor_sync(0xffffffffu, p, 2);
            if (q == 0) {
                int row = wm * 32 + mt * 16 + half * 8 + gid;
                red[row * 4 + wn] = p;
            }
        }
    }
    __syncthreads();
    if (tid < 128) {
        int row = rbase + tid;
        if (row < n) {
            float s = red[tid * 4] + red[tid * 4 + 1] + red[tid * 4 + 2] + red[tid * 4 + 3];
            out[row] = s + __ldg(linb);
        }
    }
}

// ---------------------------------------------------------------------------
// kernel_launch
// ---------------------------------------------------------------------------
extern "C" void kernel_launch(void* const* d_in, const int* in_sizes, int n_in,
                              void* d_out, int out_size) {
    (void)n_in; (void)out_size;
    const float* x    = (const float*)d_in[0];
    const int*   ei   = (const int*)d_in[1];
    const float* ew   = (const float*)d_in[2];
    const float* Wxz  = (const float*)d_in[3];
    const float* bxz  = (const float*)d_in[4];
    const float* bhz  = (const float*)d_in[6];
    const float* Wxh  = (const float*)d_in[11];
    const float* bxh  = (const float*)d_in[12];
    const float* bhh  = (const float*)d_in[14];
    const float* linW = (const float*)d_in[15];
    const float* linb = (const float*)d_in[16];
    float* out = (float*)d_out;

    int n = in_sizes[0] / FIN;   // 50000
    int e = in_sizes[2];         // 600000

    // 1) zero small buffers (dis/cnt/cur)
    k_zero_small<<<(n + 255) / 256, 256>>>(n);
    // 2) degree (by src, weighted) + histogram (by dst)
    k_deg_hist<<<(e + 255) / 256, 256>>>(ei, ew, e);
    // 3) d^{-1/2}
    k_dis<<<(n + 255) / 256, 256>>>(n);
    // 4) CSR row offsets
    k_scan<<<1, SCAN_T>>>(n);
    // 5) normalized weights + CSR scatter
    k_edgew_scatter<<<(e + 255) / 256, 256>>>(ei, ew, e);
    // 6) power-series props (gather, no atomics): S1 = Px, S2 = P S1, S3 = P S2
    int pgrid = (n * 32 + 255) / 256;
    k_prop_csr<<<pgrid, 256>>>(x, 1, n);
    k_prop_csr<<<pgrid, 256>>>(x, 2, n);
    k_prop_csr<<<pgrid, 256>>>(x, 3, n);
    // 7) weight concat
    k_wcat<<<256, 256>>>(Wxz, Wxh, bxz, bhz, bxh, bhh);
    // 8) tf32 mma GEMM + GRU epilogue + linear head
    cudaFuncSetAttribute(k_gemm_mma, cudaFuncAttributeMaxDynamicSharedMemorySize,
                         GEMM_SMEM);
    k_gemm_mma<<<(n + 127) / 128, 512, GEMM_SMEM>>>(x, linW, linb, out, n);
}

// round 8
// speedup vs baseline: 1.7296x; 1.2351x over previous
#include <cuda_runtime.h>
#include <cstdint>
#include <math.h>

// Problem constants (fixed by the dataset)
#define NMAX 50000
#define EMAX 600000
#define FIN  64
#define HID  128

// ---------------------------------------------------------------------------
// Scratch (device globals; no allocation allowed in kernel_launch)
// ---------------------------------------------------------------------------
__device__ float g_dis[NMAX];              // deg, then d^{-1/2}
__device__ int   g_cnt[NMAX];              // in-degree histogram (by dst)
__device__ int   g_cur[NMAX];              // scatter cursors
__device__ int   g_row[NMAX + 1];          // CSR row offsets (by dst)
__device__ int   g_blksum[256];            // scan block partials
__device__ int   g_src2[EMAX];             // permuted src ids
__device__ float g_w2[EMAX];               // permuted normalized weights
__device__ float g_S1[NMAX * FIN];         // P x
__device__ float g_S2[NMAX * FIN];         // P^2 x
__device__ float g_S3[NMAX * FIN];         // P^3 x
// B operand: [n' 0..255][k' 0..255], n' interleaved (even=z feat, odd=h feat),
// k' permuted within 8-groups so (k, k+4) are adjacent; values tf32-rounded.
__device__ float g_WcatT[256 * 256];
__device__ float g_bias[256];              // interleaved: [2j]=bz_j, [2j+1]=bh_j

// ---------------------------------------------------------------------------
// Setup kernels
// ---------------------------------------------------------------------------
__global__ void k_zero_small(int n) {      // dis + cnt + cur
    int i = blockIdx.x * blockDim.x + threadIdx.x;
    if (i < n) { g_dis[i] = 0.0f; g_cnt[i] = 0; g_cur[i] = 0; }
}

// deg[src] += ew (self-loops removed) ; cnt[dst] += 1
__global__ void k_deg_hist(const int* __restrict__ ei, const float* __restrict__ ew, int e) {
    int i = blockIdx.x * blockDim.x + threadIdx.x;
    if (i >= e) return;
    int s = ei[i], d = ei[e + i];
    if (s != d) atomicAdd(&g_dis[s], ew[i]);
    atomicAdd(&g_cnt[d], 1);
}

__global__ void k_dis(int n) {
    int i = blockIdx.x * blockDim.x + threadIdx.x;
    if (i < n) {
        float dg = g_dis[i];
        g_dis[i] = (dg > 0.f) ? rsqrtf(dg) : 0.f;
    }
}

// ---------------------------------------------------------------------------
// Multi-block exclusive scan of g_cnt -> g_row  (3 phases, full-chip parallel)
// All __shfl_*_sync calls are executed by FULL warps (mask 0xffffffff).
// ---------------------------------------------------------------------------
#define SCAN_BLK 512

// Phase 1: per-block exclusive scan; block totals -> g_blksum
__global__ __launch_bounds__(SCAN_BLK) void k_scan1(int n) {
    __shared__ int ws[32];                 // 32 slots; tail zero-filled
    int t = threadIdx.x;
    int i = blockIdx.x * SCAN_BLK + t;
    int v = (i < n) ? g_cnt[i] : 0;
    int lane = t & 31, w = t >> 5;
    if (t < 32) ws[t] = 0;
    __syncthreads();
    int s = v;
#pragma unroll
    for (int o = 1; o < 32; o <<= 1) {
        int u = __shfl_up_sync(0xffffffffu, s, o);
        if (lane >= o) s += u;
    }
    if (lane == 31) ws[w] = s;
    __syncthreads();
    if (w == 0) {                           // ALL 32 lanes of warp 0
        int u = ws[lane];
#pragma unroll
        for (int o = 1; o < 32; o <<= 1) {
            int z = __shfl_up_sync(0xffffffffu, u, o);
            if (lane >= o) u += z;
        }
        ws[lane] = u;
    }
    __syncthreads();
    int excl = (s - v) + (w ? ws[w - 1] : 0);
    if (i < n) g_row[i] = excl;
    if (t == SCAN_BLK - 1) g_blksum[blockIdx.x] = excl + v;
}

// Phase 2: one 128-thread block scans the <=128 block totals; writes g_row[n]
__global__ __launch_bounds__(128) void k_scan2(int n, int nblk) {
    __shared__ int ws[32];
    int t = threadIdx.x;
    int v = (t < nblk) ? g_blksum[t] : 0;
    int lane = t & 31, w = t >> 5;
    if (t < 32) ws[t] = 0;
    __syncthreads();
    int s = v;
#pragma unroll
    for (int o = 1; o < 32; o <<= 1) {
        int u = __shfl_up_sync(0xffffffffu, s, o);
        if (lane >= o) s += u;
    }
    if (lane == 31) ws[w] = s;
    __syncthreads();
    if (w == 0) {                           // ALL 32 lanes of warp 0
        int u = ws[lane];
#pragma unroll
        for (int o = 1; o < 32; o <<= 1) {
            int z = __shfl_up_sync(0xffffffffu, u, o);
            if (lane >= o) u += z;
        }
        ws[lane] = u;
    }
    __syncthreads();
    int excl = (s - v) + (w ? ws[w - 1] : 0);
    if (t < nblk) g_blksum[t] = excl;
    if (t == nblk - 1) g_row[n] = excl + v;
}

// Phase 3: add block offsets
__global__ __launch_bounds__(SCAN_BLK) void k_scan3(int n) {
    int i = blockIdx.x * SCAN_BLK + threadIdx.x;
    if (i < n) g_row[i] += g_blksum[blockIdx.x];
}

// w = -dis[src]*ew*dis[dst] (0 on self loops); scatter into CSR slots
__global__ void k_edgew_scatter(const int* __restrict__ ei, const float* __restrict__ ew, int e) {
    int i = blockIdx.x * blockDim.x + threadIdx.x;
    if (i >= e) return;
    int s = ei[i], d = ei[e + i];
    float w = (s == d) ? 0.f : -g_dis[s] * ew[i] * g_dis[d];
    int pos = g_row[d] + atomicAdd(&g_cur[d], 1);
    g_src2[pos] = s;
    g_w2[pos] = w;
}

// ---------------------------------------------------------------------------
// Gather SpMM: out[node] = sum_e w_e * in[src_e]  (one warp per node; no atomics)
// which: 1 -> x->S1 ; 2 -> S1->S2 ; 3 -> S2->S3
// ---------------------------------------------------------------------------
__global__ __launch_bounds__(256) void k_prop_csr(const float* __restrict__ x,
                                                  int which, int n) {
    int node = (blockIdx.x * blockDim.x + threadIdx.x) >> 5;
    if (node >= n) return;
    int lane = threadIdx.x & 31;
    const float* in = (which == 1) ? x : (which == 2) ? g_S1 : g_S2;
    float* out = (which == 1) ? g_S1 : (which == 2) ? g_S2 : g_S3;
    int beg = g_row[node], end = g_row[node + 1];
    float ax = 0.f, ay = 0.f;
    for (int e = beg; e < end; e++) {
        int s = __ldg(g_src2 + e);
        float wv = __ldg(g_w2 + e);
        float2 v = __ldg(reinterpret_cast<const float2*>(in + s * 64) + lane);
        ax += wv * v.x;
        ay += wv * v.y;
    }
    reinterpret_cast<float2*>(out + node * 64)[lane] = make_float2(ax, ay);
}

// ---------------------------------------------------------------------------
// tf32 round helper — destination of cvt.*.tf32 must be a b32 register.
// ---------------------------------------------------------------------------
__device__ __forceinline__ float tf32_rna(float v) {
    uint32_t r;
    asm("cvt.rna.tf32.f32 %0, %1;" : "=r"(r) : "f"(v));
    return __uint_as_float(r);
}

// ---------------------------------------------------------------------------
// Build W^T [n'][k'] with column interleave + k permutation + tf32 rounding.
// ---------------------------------------------------------------------------
__global__ void k_wcat(const float* __restrict__ Wxz, const float* __restrict__ Wxh,
                       const float* __restrict__ bxz, const float* __restrict__ bhz,
                       const float* __restrict__ bxh, const float* __restrict__ bhh) {
    int idx = blockIdx.x * blockDim.x + threadIdx.x;
    if (idx < 256 * 256) {
        int np = idx >> 8;
        int kp = idx & 255;
        int j = np >> 1;
        int g = kp >> 3, p = kp & 7;
        int kk = (p >> 1) + (p & 1) * 4;
        int k = g * 8 + kk;
        int kb = k >> 6, f = k & 63;
        float v = (np & 1) ? Wxh[kb * 64 * 128 + f * 128 + j]
                           : Wxz[kb * 64 * 128 + f * 128 + j];
        g_WcatT[np * 256 + kp] = tf32_rna(v);
    }
    if (idx < 256) {
        int j = idx >> 1;
        g_bias[idx] = (idx & 1) ? (bxh[j] + bhh[j]) : (bxz[j] + bhz[j]);
    }
}

// ---------------------------------------------------------------------------
// Legacy-mma tf32 GEMM + fused GRU epilogue + linear head.
// A columns built on the fly from power series:
//   kb0: x ; kb1: S1 ; kb2: 2*S2 - x ; kb3: 4*S3 - 3*S1
// ---------------------------------------------------------------------------
#define A_STRIDE 40
#define B_STRIDE 40
#define SM_A_FLOATS (128 * A_STRIDE)
#define SM_B_FLOATS (256 * B_STRIDE)
#define SM_RED_FLOATS (128 * 4)
#define GEMM_SMEM ((SM_A_FLOATS + SM_B_FLOATS + SM_RED_FLOATS) * 4)

__device__ __forceinline__ void mma_tf32(float* d, uint32_t a0, uint32_t a1,
                                         uint32_t a2, uint32_t a3,
                                         uint32_t b0, uint32_t b1) {
    asm volatile(
        "mma.sync.aligned.m16n8k8.row.col.f32.tf32.tf32.f32 "
        "{%0,%1,%2,%3}, {%4,%5,%6,%7}, {%8,%9}, {%0,%1,%2,%3};"
        : "+f"(d[0]), "+f"(d[1]), "+f"(d[2]), "+f"(d[3])
        : "r"(a0), "r"(a1), "r"(a2), "r"(a3), "r"(b0), "r"(b1));
}

__global__ __launch_bounds__(512, 1) void k_gemm_mma(const float* __restrict__ x,
                                                     const float* __restrict__ linW,
                                                     const float* __restrict__ linb,
                                                     float* __restrict__ out, int n) {
    extern __shared__ __align__(16) float smem[];
    float* As  = smem;                       // [128][A_STRIDE]
    float* Bs  = As + SM_A_FLOATS;           // [256][B_STRIDE]
    float* red = Bs + SM_B_FLOATS;           // [128][4]

    int tid  = threadIdx.x;
    int warp = tid >> 5;
    int lane = tid & 31;
    int wm = warp & 3;
    int wn = warp >> 2;
    int gid = lane >> 2;
    int q   = lane & 3;
    int rbase = blockIdx.x * 128;

    float acc[2][8][4];
#pragma unroll
    for (int mt = 0; mt < 2; mt++)
#pragma unroll
        for (int nt = 0; nt < 8; nt++)
#pragma unroll
            for (int c = 0; c < 4; c++) acc[mt][nt][c] = 0.f;

    int a_row  = tid >> 2;          // 0..127
    int a_quad = tid & 3;           // k-group within chunk (8 k each)
    int b_row  = tid >> 1;          // 0..255
    int b_half = tid & 1;           // 16 k' each

    for (int c = 0; c < 8; c++) {
        __syncthreads();  // previous chunk fully consumed
        // ---- stage A chunk: rows 0..127, k = c*32 .. +32, permuted + tf32 ----
        {
            int kb = c >> 1;
            int f0 = (c & 1) * 32 + a_quad * 8;
            float* dst = As + a_row * A_STRIDE + a_quad * 8;
            int grow = rbase + a_row;
            if (grow < n) {
                long off = (long)grow * 64 + f0;
                float4 v1, v2;
                if (kb == 0) {
                    v1 = __ldg(reinterpret_cast<const float4*>(x + off));
                    v2 = __ldg(reinterpret_cast<const float4*>(x + off + 4));
                } else if (kb == 1) {
                    v1 = __ldg(reinterpret_cast<const float4*>(g_S1 + off));
                    v2 = __ldg(reinterpret_cast<const float4*>(g_S1 + off + 4));
                } else if (kb == 2) {
                    float4 a1 = __ldg(reinterpret_cast<const float4*>(g_S2 + off));
                    float4 a2 = __ldg(reinterpret_cast<const float4*>(g_S2 + off + 4));
                    float4 b1 = __ldg(reinterpret_cast<const float4*>(x + off));
                    float4 b2 = __ldg(reinterpret_cast<const float4*>(x + off + 4));
                    v1 = make_float4(2.f * a1.x - b1.x, 2.f * a1.y - b1.y,
                                     2.f * a1.z - b1.z, 2.f * a1.w - b1.w);
                    v2 = make_float4(2.f * a2.x - b2.x, 2.f * a2.y - b2.y,
                                     2.f * a2.z - b2.z, 2.f * a2.w - b2.w);
                } else {
                    float4 a1 = __ldg(reinterpret_cast<const float4*>(g_S3 + off));
                    float4 a2 = __ldg(reinterpret_cast<const float4*>(g_S3 + off + 4));
                    float4 b1 = __ldg(reinterpret_cast<const float4*>(g_S1 + off));
                    float4 b2 = __ldg(reinterpret_cast<const float4*>(g_S1 + off + 4));
                    v1 = make_float4(4.f * a1.x - 3.f * b1.x, 4.f * a1.y - 3.f * b1.y,
                                     4.f * a1.z - 3.f * b1.z, 4.f * a1.w - 3.f * b1.w);
                    v2 = make_float4(4.f * a2.x - 3.f * b2.x, 4.f * a2.y - 3.f * b2.y,
                                     4.f * a2.z - 3.f * b2.z, 4.f * a2.w - 3.f * b2.w);
                }
                dst[0] = tf32_rna(v1.x); dst[2] = tf32_rna(v1.y);
                dst[4] = tf32_rna(v1.z); dst[6] = tf32_rna(v1.w);
                dst[1] = tf32_rna(v2.x); dst[3] = tf32_rna(v2.y);
                dst[5] = tf32_rna(v2.z); dst[7] = tf32_rna(v2.w);
            } else {
#pragma unroll
                for (int i = 0; i < 8; i++) dst[i] = 0.f;
            }
        }
        // ---- stage B chunk ----
        {
            const float4* src = reinterpret_cast<const float4*>(
                g_WcatT + b_row * 256 + c * 32 + b_half * 16);
            float* dst = Bs + b_row * B_STRIDE + b_half * 16;
#pragma unroll
            for (int j = 0; j < 4; j++) {
                float4 v = __ldg(src + j);
                *reinterpret_cast<float4*>(dst + j * 4) = v;
            }
        }
        __syncthreads();

        // ---- mma over 4 k-groups of 8 ----
#pragma unroll
        for (int g = 0; g < 4; g++) {
            uint32_t af[2][4];
#pragma unroll
            for (int mt = 0; mt < 2; mt++) {
                int r0 = wm * 32 + mt * 16 + gid;
                float2 lo = *reinterpret_cast<const float2*>(As + r0 * A_STRIDE + g * 8 + q * 2);
                float2 hi = *reinterpret_cast<const float2*>(As + (r0 + 8) * A_STRIDE + g * 8 + q * 2);
                af[mt][0] = __float_as_uint(lo.x);
                af[mt][2] = __float_as_uint(lo.y);
                af[mt][1] = __float_as_uint(hi.x);
                af[mt][3] = __float_as_uint(hi.y);
            }
#pragma unroll
            for (int nt = 0; nt < 8; nt++) {
                int nn = wn * 64 + nt * 8 + gid;
                float2 b = *reinterpret_cast<const float2*>(Bs + nn * B_STRIDE + g * 8 + q * 2);
                uint32_t b0 = __float_as_uint(b.x);
                uint32_t b1 = __float_as_uint(b.y);
#pragma unroll
                for (int mt = 0; mt < 2; mt++)
                    mma_tf32(acc[mt][nt], af[mt][0], af[mt][1], af[mt][2], af[mt][3], b0, b1);
            }
        }
    }

    // ---- fused epilogue ----
    float bz[8], bh[8], lw[8];
#pragma unroll
    for (int nt = 0; nt < 8; nt++) {
        int j = wn * 32 + nt * 4 + q;
        bz[nt] = __ldg(g_bias + 2 * j);
        bh[nt] = __ldg(g_bias + 2 * j + 1);
        lw[nt] = __ldg(linW + j);
    }
#pragma unroll
    for (int mt = 0; mt < 2; mt++) {
#pragma unroll
        for (int half = 0; half < 2; half++) {
            float p = 0.f;
#pragma unroll
            for (int nt = 0; nt < 8; nt++) {
                float z = acc[mt][nt][half * 2 + 0] + bz[nt];
                float h = acc[mt][nt][half * 2 + 1] + bh[nt];
                float th;
                asm("tanh.approx.f32 %0, %1;" : "=f"(th) : "f"(h));
                float sg = 1.0f / (1.0f + __expf(z));  // sigmoid(-z)
                p += fmaxf(sg * th, 0.f) * lw[nt];
            }
            p += __shfl_xor_sync(0xffffffffu, p, 1);
            p += __shfl_xor_sync(0xffffffffu, p, 2);
            if (q == 0) {
                int row = wm * 32 + mt * 16 + half * 8 + gid;
                red[row * 4 + wn] = p;
            }
        }
    }
    __syncthreads();
    if (tid < 128) {
        int row = rbase + tid;
        if (row < n) {
            float s = red[tid * 4] + red[tid * 4 + 1] + red[tid * 4 + 2] + red[tid * 4 + 3];
            out[row] = s + __ldg(linb);
        }
    }
}

// ---------------------------------------------------------------------------
// kernel_launch
// ---------------------------------------------------------------------------
extern "C" void kernel_launch(void* const* d_in, const int* in_sizes, int n_in,
                              void* d_out, int out_size) {
    (void)n_in; (void)out_size;
    const float* x    = (const float*)d_in[0];
    const int*   ei   = (const int*)d_in[1];
    const float* ew   = (const float*)d_in[2];
    const float* Wxz  = (const float*)d_in[3];
    const float* bxz  = (const float*)d_in[4];
    const float* bhz  = (const float*)d_in[6];
    const float* Wxh  = (const float*)d_in[11];
    const float* bxh  = (const float*)d_in[12];
    const float* bhh  = (const float*)d_in[14];
    const float* linW = (const float*)d_in[15];
    const float* linb = (const float*)d_in[16];
    float* out = (float*)d_out;

    int n = in_sizes[0] / FIN;   // 50000
    int e = in_sizes[2];         // 600000

    int nblk = (n + SCAN_BLK - 1) / SCAN_BLK;   // 98 for n=50000 (<=128 required)

    // 1) zero small buffers (dis/cnt/cur)
    k_zero_small<<<(n + 255) / 256, 256>>>(n);
    // 2) degree (by src, weighted) + histogram (by dst)
    k_deg_hist<<<(e + 255) / 256, 256>>>(ei, ew, e);
    // 3) d^{-1/2}
    k_dis<<<(n + 255) / 256, 256>>>(n);
    // 4) CSR row offsets: multi-block exclusive scan
    k_scan1<<<nblk, SCAN_BLK>>>(n);
    k_scan2<<<1, 128>>>(n, nblk);
    k_scan3<<<nblk, SCAN_BLK>>>(n);
    // 5) normalized weights + CSR scatter
    k_edgew_scatter<<<(e + 255) / 256, 256>>>(ei, ew, e);
    // 6) power-series props (gather, no atomics): S1 = Px, S2 = P S1, S3 = P S2
    int pgrid = (n * 32 + 255) / 256;
    k_prop_csr<<<pgrid, 256>>>(x, 1, n);
    k_prop_csr<<<pgrid, 256>>>(x, 2, n);
    k_prop_csr<<<pgrid, 256>>>(x, 3, n);
    // 7) weight concat
    k_wcat<<<256, 256>>>(Wxz, Wxh, bxz, bhz, bxh, bhh);
    // 8) tf32 mma GEMM + GRU epilogue + linear head
    cudaFuncSetAttribute(k_gemm_mma, cudaFuncAttributeMaxDynamicSharedMemorySize,
                         GEMM_SMEM);
    k_gemm_mma<<<(n + 127) / 128, 512, GEMM_SMEM>>>(x, linW, linb, out, n);
}